// round 2
// baseline (speedup 1.0000x reference)
#include <cuda_runtime.h>
#include <math.h>

#define BB  2
#define SS  2048
#define DD  4096
#define HH  32
#define HDD 128
#define MTOT (BB*SS)          // 4096 rows
#define NELEM (BB*SS*DD)      // 16,777,216

// Scratch (allocation-free rule: __device__ globals)
__device__ float g_q[NELEM];
__device__ float g_k[NELEM];
__device__ float g_v[NELEM];
__device__ float g_a[NELEM];

// ---------------------------------------------------------------------------
// SGEMM, C[m,n] = sum_k A[m,k] * W[n,k]   (row-major, K contiguous: "NT")
// 128x128 tile, BK=8, 8x8 per thread, 256 threads, register prefetch of the
// next global tile so DRAM/L2 latency hides under the FMA block.
// ---------------------------------------------------------------------------
__global__ __launch_bounds__(256) void sgemm_nt(const float* __restrict__ A,
                                                const float* __restrict__ W,
                                                float* __restrict__ C,
                                                int M, int N, int K)
{
    __shared__ float As[8][128];
    __shared__ float Bs[8][128];

    const int bm = blockIdx.y * 128;
    const int bn = blockIdx.x * 128;
    const int t  = threadIdx.x;
    const int tx = t & 15;        // 0..15
    const int ty = t >> 4;        // 0..15
    const int lrow = t >> 1;      // 0..127
    const int lcol = (t & 1) * 4; // 0 or 4

    const float* Ap = A + (size_t)(bm + lrow) * K + lcol;
    const float* Wp = W + (size_t)(bn + lrow) * K + lcol;

    float acc[8][8];
#pragma unroll
    for (int i = 0; i < 8; i++)
#pragma unroll
        for (int j = 0; j < 8; j++) acc[i][j] = 0.f;

    float4 a4 = *(const float4*)(Ap);
    float4 b4 = *(const float4*)(Wp);

    for (int kt = 0; kt < K; kt += 8) {
        __syncthreads();
        As[lcol+0][lrow] = a4.x; As[lcol+1][lrow] = a4.y;
        As[lcol+2][lrow] = a4.z; As[lcol+3][lrow] = a4.w;
        Bs[lcol+0][lrow] = b4.x; Bs[lcol+1][lrow] = b4.y;
        Bs[lcol+2][lrow] = b4.z; Bs[lcol+3][lrow] = b4.w;
        __syncthreads();
        if (kt + 8 < K) {                       // prefetch next tile
            a4 = *(const float4*)(Ap + kt + 8);
            b4 = *(const float4*)(Wp + kt + 8);
        }
#pragma unroll
        for (int kk = 0; kk < 8; kk++) {
            float a[8], b[8];
#pragma unroll
            for (int i = 0; i < 8; i++) a[i] = As[kk][ty*8 + i];
#pragma unroll
            for (int j = 0; j < 8; j++) b[j] = Bs[kk][tx*8 + j];
#pragma unroll
            for (int i = 0; i < 8; i++)
#pragma unroll
                for (int j = 0; j < 8; j++) acc[i][j] += a[i] * b[j];
        }
    }

#pragma unroll
    for (int i = 0; i < 8; i++) {
        float* cp = C + (size_t)(bm + ty*8 + i) * N + bn + tx*8;
        ((float4*)cp)[0] = make_float4(acc[i][0], acc[i][1], acc[i][2], acc[i][3]);
        ((float4*)cp)[1] = make_float4(acc[i][4], acc[i][5], acc[i][6], acc[i][7]);
    }
}

// Fused QKV: blockIdx.z selects {wq->g_q, wk->g_k, wv->g_v}.
__global__ __launch_bounds__(256) void sgemm_qkv(const float* __restrict__ A,
                                                 const float* __restrict__ Wq,
                                                 const float* __restrict__ Wk,
                                                 const float* __restrict__ Wv)
{
    __shared__ float As[8][128];
    __shared__ float Bs[8][128];

    const float* W = (blockIdx.z == 0) ? Wq : (blockIdx.z == 1) ? Wk : Wv;
    float* C = (blockIdx.z == 0) ? g_q : (blockIdx.z == 1) ? g_k : g_v;

    const int K = DD, N = DD;
    const int bm = blockIdx.y * 128;
    const int bn = blockIdx.x * 128;
    const int t  = threadIdx.x;
    const int tx = t & 15;
    const int ty = t >> 4;
    const int lrow = t >> 1;
    const int lcol = (t & 1) * 4;

    const float* Ap = A + (size_t)(bm + lrow) * K + lcol;
    const float* Wp = W + (size_t)(bn + lrow) * K + lcol;

    float acc[8][8];
#pragma unroll
    for (int i = 0; i < 8; i++)
#pragma unroll
        for (int j = 0; j < 8; j++) acc[i][j] = 0.f;

    float4 a4 = *(const float4*)(Ap);
    float4 b4 = *(const float4*)(Wp);

    for (int kt = 0; kt < K; kt += 8) {
        __syncthreads();
        As[lcol+0][lrow] = a4.x; As[lcol+1][lrow] = a4.y;
        As[lcol+2][lrow] = a4.z; As[lcol+3][lrow] = a4.w;
        Bs[lcol+0][lrow] = b4.x; Bs[lcol+1][lrow] = b4.y;
        Bs[lcol+2][lrow] = b4.z; Bs[lcol+3][lrow] = b4.w;
        __syncthreads();
        if (kt + 8 < K) {
            a4 = *(const float4*)(Ap + kt + 8);
            b4 = *(const float4*)(Wp + kt + 8);
        }
#pragma unroll
        for (int kk = 0; kk < 8; kk++) {
            float a[8], b[8];
#pragma unroll
            for (int i = 0; i < 8; i++) a[i] = As[kk][ty*8 + i];
#pragma unroll
            for (int j = 0; j < 8; j++) b[j] = Bs[kk][tx*8 + j];
#pragma unroll
            for (int i = 0; i < 8; i++)
#pragma unroll
                for (int j = 0; j < 8; j++) acc[i][j] += a[i] * b[j];
        }
    }

#pragma unroll
    for (int i = 0; i < 8; i++) {
        float* cp = C + (size_t)(bm + ty*8 + i) * N + bn + tx*8;
        ((float4*)cp)[0] = make_float4(acc[i][0], acc[i][1], acc[i][2], acc[i][3]);
        ((float4*)cp)[1] = make_float4(acc[i][4], acc[i][5], acc[i][6], acc[i][7]);
    }
}

// ---------------------------------------------------------------------------
// RoPE on Q and K in-place. One thread per (b,s,h,pair).
// ---------------------------------------------------------------------------
__global__ void rope_kernel(float* __restrict__ q, float* __restrict__ k,
                            const float* __restrict__ cosT,
                            const float* __restrict__ sinT)
{
    int i = blockIdx.x * blockDim.x + threadIdx.x;   // 0 .. 2^23-1
    int pair = i & 63;
    int s    = (i >> 11) & 2047;
    int b    = i >> 22;
    int h    = (i >> 6) & 31;

    float c  = cosT[s*64 + pair];
    float sn = sinT[s*64 + pair];

    size_t off = ((size_t)(b*SS + s))*DD + h*HDD + pair*2;
    float2 qv = *(float2*)(q + off);
    float2 kv = *(float2*)(k + off);
    *(float2*)(q + off) = make_float2(qv.x*c - qv.y*sn, qv.x*sn + qv.y*c);
    *(float2*)(k + off) = make_float2(kv.x*c - kv.y*sn, kv.x*sn + kv.y*c);
}

// ---------------------------------------------------------------------------
// Flash attention (causal, exact fp32). One CTA = 64 query rows of one (b,h).
// 8 warps, 8 rows per warp. smem: Qs[64][128] Kt[128][64] Vs[64][128] Ps[64][64]
// = 112 KB dynamic.
// ---------------------------------------------------------------------------
__global__ __launch_bounds__(256) void flash_attn(const float* __restrict__ Q,
                                                  const float* __restrict__ K,
                                                  const float* __restrict__ V,
                                                  float* __restrict__ O)
{
    extern __shared__ float sm[];
    float* Qs = sm;                  // 64*128
    float* Kt = Qs + 64*128;         // 128*64 : Kt[d*64 + j]
    float* Vs = Kt + 128*64;         // 64*128
    float* Ps = Vs + 64*128;         // 64*64

    const int b  = blockIdx.z;
    const int h  = blockIdx.y;
    const int q0 = blockIdx.x * 64;
    const int t    = threadIdx.x;
    const int w    = t >> 5;
    const int lane = t & 31;

    // Load Q tile: 4 threads per row, 32 dims each.
    {
        int r  = t >> 2;
        int c0 = (t & 3) * 32;
        const float* src = Q + ((size_t)(b*SS + q0 + r))*DD + h*HDD + c0;
        float* dst = Qs + r*128 + c0;
#pragma unroll
        for (int i = 0; i < 8; i++) ((float4*)dst)[i] = ((const float4*)src)[i];
    }

    float m[8], l[8], o[8][4];
#pragma unroll
    for (int rr = 0; rr < 8; rr++) {
        m[rr] = -INFINITY; l[rr] = 0.f;
        o[rr][0] = o[rr][1] = o[rr][2] = o[rr][3] = 0.f;
    }

    const float scale = 0.08838834764831845f;  // 1/sqrt(128)
    const int ntiles = q0/64 + 1;              // causal

    for (int kt = 0; kt < ntiles; kt++) {
        const int j0 = kt * 64;
        __syncthreads();
        {
            int r  = t >> 2;
            int c0 = (t & 3) * 32;
            size_t base = ((size_t)(b*SS + j0 + r))*DD + h*HDD + c0;
            const float* ksrc = K + base;
            const float* vsrc = V + base;
            float* vdst = Vs + r*128 + c0;
#pragma unroll
            for (int i = 0; i < 8; i++) {
                float4 kv = ((const float4*)ksrc)[i];
                int d = c0 + i*4;
                Kt[(d+0)*64 + r] = kv.x;
                Kt[(d+1)*64 + r] = kv.y;
                Kt[(d+2)*64 + r] = kv.z;
                Kt[(d+3)*64 + r] = kv.w;
                ((float4*)vdst)[i] = ((const float4*)vsrc)[i];
            }
        }
        __syncthreads();

        // ---- scores ----
        float s0[8], s1[8];
#pragma unroll
        for (int rr = 0; rr < 8; rr++) { s0[rr] = 0.f; s1[rr] = 0.f; }
#pragma unroll 4
        for (int d = 0; d < 128; d++) {
            float kv0 = Kt[d*64 + lane];
            float kv1 = Kt[d*64 + lane + 32];
#pragma unroll
            for (int rr = 0; rr < 8; rr++) {
                float qv = Qs[(w*8 + rr)*128 + d];
                s0[rr] += qv * kv0;
                s1[rr] += qv * kv1;
            }
        }

        // ---- online softmax ----
#pragma unroll
        for (int rr = 0; rr < 8; rr++) {
            int ig  = q0 + w*8 + rr;
            int jg0 = j0 + lane;
            int jg1 = j0 + lane + 32;
            float v0 = (jg0 <= ig) ? s0[rr]*scale : -INFINITY;
            float v1 = (jg1 <= ig) ? s1[rr]*scale : -INFINITY;
            float tmax = fmaxf(v0, v1);
#pragma unroll
            for (int off = 16; off; off >>= 1)
                tmax = fmaxf(tmax, __shfl_xor_sync(0xffffffffu, tmax, off));
            float newm = fmaxf(m[rr], tmax);
            float p0 = __expf(v0 - newm);
            float p1 = __expf(v1 - newm);
            float psum = p0 + p1;
#pragma unroll
            for (int off = 16; off; off >>= 1)
                psum += __shfl_xor_sync(0xffffffffu, psum, off);
            float corr = __expf(m[rr] - newm);
            l[rr] = l[rr]*corr + psum;
            m[rr] = newm;
            o[rr][0] *= corr; o[rr][1] *= corr; o[rr][2] *= corr; o[rr][3] *= corr;
            Ps[(w*8 + rr)*64 + lane]      = p0;
            Ps[(w*8 + rr)*64 + lane + 32] = p1;
        }
        __syncwarp();

        // ---- o += P @ V ----  (each warp reads only its own Ps rows)
        for (int j = 0; j < 64; j++) {
            float v0 = Vs[j*128 + lane];
            float v1 = Vs[j*128 + lane + 32];
            float v2 = Vs[j*128 + lane + 64];
            float v3 = Vs[j*128 + lane + 96];
#pragma unroll
            for (int rr = 0; rr < 8; rr++) {
                float p = Ps[(w*8 + rr)*64 + j];
                o[rr][0] += p*v0; o[rr][1] += p*v1;
                o[rr][2] += p*v2; o[rr][3] += p*v3;
            }
        }
    }

    // ---- normalize + write ----
#pragma unroll
    for (int rr = 0; rr < 8; rr++) {
        float inv = 1.f / l[rr];
        size_t base = ((size_t)(b*SS + q0 + w*8 + rr))*DD + h*HDD + lane;
        O[base +  0] = o[rr][0] * inv;
        O[base + 32] = o[rr][1] * inv;
        O[base + 64] = o[rr][2] * inv;
        O[base + 96] = o[rr][3] * inv;
    }
}

// ---------------------------------------------------------------------------
// kernel_launch. inputs: 0:x 1:freqs_cos 2:freqs_sin 3:mask 4:wq 5:wk 6:wv
// 7:wo 8:cache_k 9:cache_v 10:start_pos. start_pos=0; hard causal mask is
// bit-identical to softmax(x - 1e9) in fp32 (exp underflows to 0 exactly).
// ---------------------------------------------------------------------------
extern "C" void kernel_launch(void* const* d_in, const int* in_sizes, int n_in,
                              void* d_out, int out_size)
{
    const float* x  = (const float*)d_in[0];
    const float* fc = (const float*)d_in[1];
    const float* fs = (const float*)d_in[2];
    const float* wq = (const float*)d_in[4];
    const float* wk = (const float*)d_in[5];
    const float* wv = (const float*)d_in[6];
    const float* wo = (const float*)d_in[7];
    float* out = (float*)d_out;

    float *q, *k, *v, *a;
    cudaGetSymbolAddress((void**)&q, g_q);
    cudaGetSymbolAddress((void**)&k, g_k);
    cudaGetSymbolAddress((void**)&v, g_v);
    cudaGetSymbolAddress((void**)&a, g_a);

    static bool attr_done = false;
    if (!attr_done) {
        cudaFuncSetAttribute(flash_attn, cudaFuncAttributeMaxDynamicSharedMemorySize, 114688);
        attr_done = true;
    }

    sgemm_qkv<<<dim3(DD/128, MTOT/128, 3), 256>>>(x, wq, wk, wv);

    rope_kernel<<<(BB*SS*HH*64)/256, 256>>>(q, k, fc, fs);

    flash_attn<<<dim3(SS/64, HH, BB), 256, 114688>>>(q, k, v, a);

    sgemm_nt<<<dim3(DD/128, MTOT/128), 256>>>(a, wo, out, MTOT, DD, DD);
}

// round 4
// speedup vs baseline: 1.0001x; 1.0001x over previous
#include <cuda_runtime.h>
#include <math.h>

#define BB  2
#define SS  2048
#define DD  4096
#define HH  32
#define HDD 128
#define MTOT (BB*SS)          // 4096 rows
#define NELEM (BB*SS*DD)      // 16,777,216

// Scratch (allocation-free rule: __device__ globals)
__device__ float g_q[NELEM];
__device__ float g_k[NELEM];
__device__ float g_v[NELEM];
__device__ float g_a[NELEM];

// ---------------------------------------------------------------------------
// SGEMM, C[m,n] = sum_k A[m,k] * W[n,k]   (row-major, K contiguous: "NT")
// 128x128 tile, BK=8, 8x8 per thread, 256 threads, register prefetch of the
// next global tile so DRAM/L2 latency hides under the FMA block.
// ---------------------------------------------------------------------------
__global__ __launch_bounds__(256) void sgemm_nt(const float* __restrict__ A,
                                                const float* __restrict__ W,
                                                float* __restrict__ C,
                                                int M, int N, int K)
{
    __shared__ float As[8][128];
    __shared__ float Bs[8][128];

    const int bm = blockIdx.y * 128;
    const int bn = blockIdx.x * 128;
    const int t  = threadIdx.x;
    const int tx = t & 15;        // 0..15
    const int ty = t >> 4;        // 0..15
    const int lrow = t >> 1;      // 0..127
    const int lcol = (t & 1) * 4; // 0 or 4

    const float* Ap = A + (size_t)(bm + lrow) * K + lcol;
    const float* Wp = W + (size_t)(bn + lrow) * K + lcol;

    float acc[8][8];
#pragma unroll
    for (int i = 0; i < 8; i++)
#pragma unroll
        for (int j = 0; j < 8; j++) acc[i][j] = 0.f;

    float4 a4 = *(const float4*)(Ap);
    float4 b4 = *(const float4*)(Wp);

    for (int kt = 0; kt < K; kt += 8) {
        __syncthreads();
        As[lcol+0][lrow] = a4.x; As[lcol+1][lrow] = a4.y;
        As[lcol+2][lrow] = a4.z; As[lcol+3][lrow] = a4.w;
        Bs[lcol+0][lrow] = b4.x; Bs[lcol+1][lrow] = b4.y;
        Bs[lcol+2][lrow] = b4.z; Bs[lcol+3][lrow] = b4.w;
        __syncthreads();
        if (kt + 8 < K) {                       // prefetch next tile
            a4 = *(const float4*)(Ap + kt + 8);
            b4 = *(const float4*)(Wp + kt + 8);
        }
#pragma unroll
        for (int kk = 0; kk < 8; kk++) {
            float a[8], b[8];
#pragma unroll
            for (int i = 0; i < 8; i++) a[i] = As[kk][ty*8 + i];
#pragma unroll
            for (int j = 0; j < 8; j++) b[j] = Bs[kk][tx*8 + j];
#pragma unroll
            for (int i = 0; i < 8; i++)
#pragma unroll
                for (int j = 0; j < 8; j++) acc[i][j] += a[i] * b[j];
        }
    }

#pragma unroll
    for (int i = 0; i < 8; i++) {
        float* cp = C + (size_t)(bm + ty*8 + i) * N + bn + tx*8;
        ((float4*)cp)[0] = make_float4(acc[i][0], acc[i][1], acc[i][2], acc[i][3]);
        ((float4*)cp)[1] = make_float4(acc[i][4], acc[i][5], acc[i][6], acc[i][7]);
    }
}

// Fused QKV: blockIdx.z selects {wq->g_q, wk->g_k, wv->g_v}.
__global__ __launch_bounds__(256) void sgemm_qkv(const float* __restrict__ A,
                                                 const float* __restrict__ Wq,
                                                 const float* __restrict__ Wk,
                                                 const float* __restrict__ Wv)
{
    __shared__ float As[8][128];
    __shared__ float Bs[8][128];

    const float* W = (blockIdx.z == 0) ? Wq : (blockIdx.z == 1) ? Wk : Wv;
    float* C = (blockIdx.z == 0) ? g_q : (blockIdx.z == 1) ? g_k : g_v;

    const int K = DD, N = DD;
    const int bm = blockIdx.y * 128;
    const int bn = blockIdx.x * 128;
    const int t  = threadIdx.x;
    const int tx = t & 15;
    const int ty = t >> 4;
    const int lrow = t >> 1;
    const int lcol = (t & 1) * 4;

    const float* Ap = A + (size_t)(bm + lrow) * K + lcol;
    const float* Wp = W + (size_t)(bn + lrow) * K + lcol;

    float acc[8][8];
#pragma unroll
    for (int i = 0; i < 8; i++)
#pragma unroll
        for (int j = 0; j < 8; j++) acc[i][j] = 0.f;

    float4 a4 = *(const float4*)(Ap);
    float4 b4 = *(const float4*)(Wp);

    for (int kt = 0; kt < K; kt += 8) {
        __syncthreads();
        As[lcol+0][lrow] = a4.x; As[lcol+1][lrow] = a4.y;
        As[lcol+2][lrow] = a4.z; As[lcol+3][lrow] = a4.w;
        Bs[lcol+0][lrow] = b4.x; Bs[lcol+1][lrow] = b4.y;
        Bs[lcol+2][lrow] = b4.z; Bs[lcol+3][lrow] = b4.w;
        __syncthreads();
        if (kt + 8 < K) {
            a4 = *(const float4*)(Ap + kt + 8);
            b4 = *(const float4*)(Wp + kt + 8);
        }
#pragma unroll
        for (int kk = 0; kk < 8; kk++) {
            float a[8], b[8];
#pragma unroll
            for (int i = 0; i < 8; i++) a[i] = As[kk][ty*8 + i];
#pragma unroll
            for (int j = 0; j < 8; j++) b[j] = Bs[kk][tx*8 + j];
#pragma unroll
            for (int i = 0; i < 8; i++)
#pragma unroll
                for (int j = 0; j < 8; j++) acc[i][j] += a[i] * b[j];
        }
    }

#pragma unroll
    for (int i = 0; i < 8; i++) {
        float* cp = C + (size_t)(bm + ty*8 + i) * N + bn + tx*8;
        ((float4*)cp)[0] = make_float4(acc[i][0], acc[i][1], acc[i][2], acc[i][3]);
        ((float4*)cp)[1] = make_float4(acc[i][4], acc[i][5], acc[i][6], acc[i][7]);
    }
}

// ---------------------------------------------------------------------------
// RoPE on Q and K in-place. One thread per (b,s,h,pair).
// ---------------------------------------------------------------------------
__global__ void rope_kernel(float* __restrict__ q, float* __restrict__ k,
                            const float* __restrict__ cosT,
                            const float* __restrict__ sinT)
{
    int i = blockIdx.x * blockDim.x + threadIdx.x;   // 0 .. 2^23-1
    int pair = i & 63;
    int s    = (i >> 11) & 2047;
    int b    = i >> 22;
    int h    = (i >> 6) & 31;

    float c  = cosT[s*64 + pair];
    float sn = sinT[s*64 + pair];

    size_t off = ((size_t)(b*SS + s))*DD + h*HDD + pair*2;
    float2 qv = *(float2*)(q + off);
    float2 kv = *(float2*)(k + off);
    *(float2*)(q + off) = make_float2(qv.x*c - qv.y*sn, qv.x*sn + qv.y*c);
    *(float2*)(k + off) = make_float2(kv.x*c - kv.y*sn, kv.x*sn + kv.y*c);
}

// ---------------------------------------------------------------------------
// Flash attention (causal, exact fp32). One CTA = 64 query rows of one (b,h).
// 8 warps, 8 rows per warp. smem: Qs[64][128] Kt[128][64] Vs[64][128] Ps[64][64]
// = 112 KB dynamic.
// ---------------------------------------------------------------------------
__global__ __launch_bounds__(256) void flash_attn(const float* __restrict__ Q,
                                                  const float* __restrict__ K,
                                                  const float* __restrict__ V,
                                                  float* __restrict__ O)
{
    extern __shared__ float sm[];
    float* Qs = sm;                  // 64*128
    float* Kt = Qs + 64*128;         // 128*64 : Kt[d*64 + j]
    float* Vs = Kt + 128*64;         // 64*128
    float* Ps = Vs + 64*128;         // 64*64

    const int b  = blockIdx.z;
    const int h  = blockIdx.y;
    const int q0 = blockIdx.x * 64;
    const int t    = threadIdx.x;
    const int w    = t >> 5;
    const int lane = t & 31;

    // Load Q tile: 4 threads per row, 32 dims each.
    {
        int r  = t >> 2;
        int c0 = (t & 3) * 32;
        const float* src = Q + ((size_t)(b*SS + q0 + r))*DD + h*HDD + c0;
        float* dst = Qs + r*128 + c0;
#pragma unroll
        for (int i = 0; i < 8; i++) ((float4*)dst)[i] = ((const float4*)src)[i];
    }

    float m[8], l[8], o[8][4];
#pragma unroll
    for (int rr = 0; rr < 8; rr++) {
        m[rr] = -INFINITY; l[rr] = 0.f;
        o[rr][0] = o[rr][1] = o[rr][2] = o[rr][3] = 0.f;
    }

    const float scale = 0.08838834764831845f;  // 1/sqrt(128)
    const int ntiles = q0/64 + 1;              // causal

    for (int kt = 0; kt < ntiles; kt++) {
        const int j0 = kt * 64;
        __syncthreads();
        {
            int r  = t >> 2;
            int c0 = (t & 3) * 32;
            size_t base = ((size_t)(b*SS + j0 + r))*DD + h*HDD + c0;
            const float* ksrc = K + base;
            const float* vsrc = V + base;
            float* vdst = Vs + r*128 + c0;
#pragma unroll
            for (int i = 0; i < 8; i++) {
                float4 kv = ((const float4*)ksrc)[i];
                int d = c0 + i*4;
                Kt[(d+0)*64 + r] = kv.x;
                Kt[(d+1)*64 + r] = kv.y;
                Kt[(d+2)*64 + r] = kv.z;
                Kt[(d+3)*64 + r] = kv.w;
                ((float4*)vdst)[i] = ((const float4*)vsrc)[i];
            }
        }
        __syncthreads();

        // ---- scores ----
        float s0[8], s1[8];
#pragma unroll
        for (int rr = 0; rr < 8; rr++) { s0[rr] = 0.f; s1[rr] = 0.f; }
#pragma unroll 4
        for (int d = 0; d < 128; d++) {
            float kv0 = Kt[d*64 + lane];
            float kv1 = Kt[d*64 + lane + 32];
#pragma unroll
            for (int rr = 0; rr < 8; rr++) {
                float qv = Qs[(w*8 + rr)*128 + d];
                s0[rr] += qv * kv0;
                s1[rr] += qv * kv1;
            }
        }

        // ---- online softmax ----
#pragma unroll
        for (int rr = 0; rr < 8; rr++) {
            int ig  = q0 + w*8 + rr;
            int jg0 = j0 + lane;
            int jg1 = j0 + lane + 32;
            float v0 = (jg0 <= ig) ? s0[rr]*scale : -INFINITY;
            float v1 = (jg1 <= ig) ? s1[rr]*scale : -INFINITY;
            float tmax = fmaxf(v0, v1);
#pragma unroll
            for (int off = 16; off; off >>= 1)
                tmax = fmaxf(tmax, __shfl_xor_sync(0xffffffffu, tmax, off));
            float newm = fmaxf(m[rr], tmax);
            float p0 = __expf(v0 - newm);
            float p1 = __expf(v1 - newm);
            float psum = p0 + p1;
#pragma unroll
            for (int off = 16; off; off >>= 1)
                psum += __shfl_xor_sync(0xffffffffu, psum, off);
            float corr = __expf(m[rr] - newm);
            l[rr] = l[rr]*corr + psum;
            m[rr] = newm;
            o[rr][0] *= corr; o[rr][1] *= corr; o[rr][2] *= corr; o[rr][3] *= corr;
            Ps[(w*8 + rr)*64 + lane]      = p0;
            Ps[(w*8 + rr)*64 + lane + 32] = p1;
        }
        __syncwarp();

        // ---- o += P @ V ----  (each warp reads only its own Ps rows)
        for (int j = 0; j < 64; j++) {
            float v0 = Vs[j*128 + lane];
            float v1 = Vs[j*128 + lane + 32];
            float v2 = Vs[j*128 + lane + 64];
            float v3 = Vs[j*128 + lane + 96];
#pragma unroll
            for (int rr = 0; rr < 8; rr++) {
                float p = Ps[(w*8 + rr)*64 + j];
                o[rr][0] += p*v0; o[rr][1] += p*v1;
                o[rr][2] += p*v2; o[rr][3] += p*v3;
            }
        }
    }

    // ---- normalize + write ----
#pragma unroll
    for (int rr = 0; rr < 8; rr++) {
        float inv = 1.f / l[rr];
        size_t base = ((size_t)(b*SS + q0 + w*8 + rr))*DD + h*HDD + lane;
        O[base +  0] = o[rr][0] * inv;
        O[base + 32] = o[rr][1] * inv;
        O[base + 64] = o[rr][2] * inv;
        O[base + 96] = o[rr][3] * inv;
    }
}

// ---------------------------------------------------------------------------
// kernel_launch. inputs: 0:x 1:freqs_cos 2:freqs_sin 3:mask 4:wq 5:wk 6:wv
// 7:wo 8:cache_k 9:cache_v 10:start_pos. start_pos=0; hard causal mask is
// bit-identical to softmax(x - 1e9) in fp32 (exp underflows to 0 exactly).
// ---------------------------------------------------------------------------
extern "C" void kernel_launch(void* const* d_in, const int* in_sizes, int n_in,
                              void* d_out, int out_size)
{
    const float* x  = (const float*)d_in[0];
    const float* fc = (const float*)d_in[1];
    const float* fs = (const float*)d_in[2];
    const float* wq = (const float*)d_in[4];
    const float* wk = (const float*)d_in[5];
    const float* wv = (const float*)d_in[6];
    const float* wo = (const float*)d_in[7];
    float* out = (float*)d_out;

    float *q, *k, *v, *a;
    cudaGetSymbolAddress((void**)&q, g_q);
    cudaGetSymbolAddress((void**)&k, g_k);
    cudaGetSymbolAddress((void**)&v, g_v);
    cudaGetSymbolAddress((void**)&a, g_a);

    static bool attr_done = false;
    if (!attr_done) {
        cudaFuncSetAttribute(flash_attn, cudaFuncAttributeMaxDynamicSharedMemorySize, 114688);
        attr_done = true;
    }

    sgemm_qkv<<<dim3(DD/128, MTOT/128, 3), 256>>>(x, wq, wk, wv);

    rope_kernel<<<(BB*SS*HH*64)/256, 256>>>(q, k, fc, fs);

    flash_attn<<<dim3(SS/64, HH, BB), 256, 114688>>>(q, k, v, a);

    sgemm_nt<<<dim3(DD/128, MTOT/128), 256>>>(a, wo, out, MTOT, DD, DD);
}

// round 5
// speedup vs baseline: 1.2470x; 1.2469x over previous
#include <cuda_runtime.h>
#include <cuda_bf16.h>
#include <math.h>
#include <stdint.h>

#define BB  2
#define SS  2048
#define DD  4096
#define HH  32
#define HDD 128
#define MTOT (BB*SS)          // 4096 rows
#define NELEM (BB*SS*DD)      // 16,777,216

#define AST 40                // smem bf16 row stride (32 + 8 pad)

// Scratch (allocation-free rule: __device__ globals)
__device__ float g_q[NELEM];
__device__ float g_k[NELEM];
__device__ float g_v[NELEM];
__device__ float g_a[NELEM];

#define MMA16816(d, a, b)                                                   \
    asm volatile("mma.sync.aligned.m16n8k16.row.col.f32.bf16.bf16.f32 "     \
                 "{%0,%1,%2,%3}, {%4,%5,%6,%7}, {%8,%9}, {%0,%1,%2,%3};"    \
                 : "+f"(d[0]), "+f"(d[1]), "+f"(d[2]), "+f"(d[3])           \
                 : "r"(a[0]), "r"(a[1]), "r"(a[2]), "r"(a[3]),              \
                   "r"(b[0]), "r"(b[1]))

// ---------------------------------------------------------------------------
// Split-bf16 tensor-core GEMM core: C[m,n] = sum_k A[m,k]*W[n,k]  ("NT").
// Each fp32 operand split into hi+lo bf16; acc += ah*bh + ah*bl + al*bh in
// fp32 mma accumulators -> ~1e-5 relative accuracy.
// CTA tile 128x128, BK=32, 256 threads, warp tile 64x32.
// ---------------------------------------------------------------------------
__device__ __forceinline__ void gemm_core(const float* __restrict__ A,
                                          const float* __restrict__ W,
                                          float* __restrict__ C,
                                          int K, int N, int bm, int bn)
{
    __shared__ __nv_bfloat16 Ah[128][AST];
    __shared__ __nv_bfloat16 Al[128][AST];
    __shared__ __nv_bfloat16 Wh[128][AST];
    __shared__ __nv_bfloat16 Wl[128][AST];

    const int t    = threadIdx.x;
    const int lane = t & 31;
    const int w    = t >> 5;
    const int wm   = (w & 1) * 64;   // warp m-offset within CTA tile
    const int wn   = (w >> 1) * 32;  // warp n-offset

    // global->smem staging: thread loads 16 consecutive floats of one row
    const int lr = t >> 1;           // 0..127
    const int lc = (t & 1) * 16;     // 0 or 16

    const float* Ap = A + (size_t)(bm + lr) * K + lc;
    const float* Wp = W + (size_t)(bn + lr) * K + lc;

    float acc[4][4][4];
#pragma unroll
    for (int mt = 0; mt < 4; mt++)
#pragma unroll
        for (int nt = 0; nt < 4; nt++)
#pragma unroll
            for (int r = 0; r < 4; r++) acc[mt][nt][r] = 0.f;

    float ar[16], wr[16];
#pragma unroll
    for (int i = 0; i < 16; i += 4) {
        *(float4*)(ar + i) = *(const float4*)(Ap + i);
        *(float4*)(wr + i) = *(const float4*)(Wp + i);
    }

    for (int kt = 0; kt < K; kt += 32) {
        __syncthreads();
#pragma unroll
        for (int i = 0; i < 16; i++) {
            __nv_bfloat16 h = __float2bfloat16_rn(ar[i]);
            Ah[lr][lc + i] = h;
            Al[lr][lc + i] = __float2bfloat16_rn(ar[i] - __bfloat162float(h));
            __nv_bfloat16 g = __float2bfloat16_rn(wr[i]);
            Wh[lr][lc + i] = g;
            Wl[lr][lc + i] = __float2bfloat16_rn(wr[i] - __bfloat162float(g));
        }
        __syncthreads();
        if (kt + 32 < K) {   // prefetch next k-slab while MMAs run
#pragma unroll
            for (int i = 0; i < 16; i += 4) {
                *(float4*)(ar + i) = *(const float4*)(Ap + kt + 32 + i);
                *(float4*)(wr + i) = *(const float4*)(Wp + kt + 32 + i);
            }
        }

#pragma unroll
        for (int ks = 0; ks < 32; ks += 16) {
            // B fragments for 4 n-tiles (hi and lo)
            uint32_t bh[4][2], bl[4][2];
            const int bcol = wn + (lane >> 2);
            const int bk   = ks + (lane & 3) * 2;
#pragma unroll
            for (int nt = 0; nt < 4; nt++) {
                bh[nt][0] = *(const uint32_t*)&Wh[bcol + nt * 8][bk];
                bh[nt][1] = *(const uint32_t*)&Wh[bcol + nt * 8][bk + 8];
                bl[nt][0] = *(const uint32_t*)&Wl[bcol + nt * 8][bk];
                bl[nt][1] = *(const uint32_t*)&Wl[bcol + nt * 8][bk + 8];
            }
            const int arow = wm + (lane >> 2);
            const int ak   = ks + (lane & 3) * 2;
#pragma unroll
            for (int mt = 0; mt < 4; mt++) {
                uint32_t ah[4], al[4];
                ah[0] = *(const uint32_t*)&Ah[arow + mt * 16][ak];
                ah[1] = *(const uint32_t*)&Ah[arow + mt * 16 + 8][ak];
                ah[2] = *(const uint32_t*)&Ah[arow + mt * 16][ak + 8];
                ah[3] = *(const uint32_t*)&Ah[arow + mt * 16 + 8][ak + 8];
                al[0] = *(const uint32_t*)&Al[arow + mt * 16][ak];
                al[1] = *(const uint32_t*)&Al[arow + mt * 16 + 8][ak];
                al[2] = *(const uint32_t*)&Al[arow + mt * 16][ak + 8];
                al[3] = *(const uint32_t*)&Al[arow + mt * 16 + 8][ak + 8];
#pragma unroll
                for (int nt = 0; nt < 4; nt++) {
                    MMA16816(acc[mt][nt], ah, bh[nt]);   // hi*hi
                    MMA16816(acc[mt][nt], ah, bl[nt]);   // hi*lo
                    MMA16816(acc[mt][nt], al, bh[nt]);   // lo*hi
                }
            }
        }
    }

    // epilogue: fp32 direct to global
    const int row = lane >> 2;
    const int col = (lane & 3) * 2;
#pragma unroll
    for (int mt = 0; mt < 4; mt++)
#pragma unroll
        for (int nt = 0; nt < 4; nt++) {
            float* cp = C + (size_t)(bm + wm + mt * 16 + row) * N + bn + wn + nt * 8 + col;
            *(float2*)cp             = make_float2(acc[mt][nt][0], acc[mt][nt][1]);
            *(float2*)(cp + 8 * (size_t)N) = make_float2(acc[mt][nt][2], acc[mt][nt][3]);
        }
}

__global__ __launch_bounds__(256) void bgemm_nt(const float* __restrict__ A,
                                                const float* __restrict__ W,
                                                float* __restrict__ C,
                                                int K, int N)
{
    gemm_core(A, W, C, K, N, blockIdx.y * 128, blockIdx.x * 128);
}

// Fused QKV: blockIdx.z selects {wq->g_q, wk->g_k, wv->g_v}; x tiles stay hot in L2.
__global__ __launch_bounds__(256) void bgemm_qkv(const float* __restrict__ A,
                                                 const float* __restrict__ Wq,
                                                 const float* __restrict__ Wk,
                                                 const float* __restrict__ Wv)
{
    const float* W = (blockIdx.z == 0) ? Wq : (blockIdx.z == 1) ? Wk : Wv;
    float* C       = (blockIdx.z == 0) ? g_q : (blockIdx.z == 1) ? g_k : g_v;
    gemm_core(A, W, C, DD, DD, blockIdx.y * 128, blockIdx.x * 128);
}

// ---------------------------------------------------------------------------
// RoPE on Q and K in-place. One thread per (b,s,h,pair).
// ---------------------------------------------------------------------------
__global__ void rope_kernel(float* __restrict__ q, float* __restrict__ k,
                            const float* __restrict__ cosT,
                            const float* __restrict__ sinT)
{
    int i = blockIdx.x * blockDim.x + threadIdx.x;   // 0 .. 2^23-1
    int pair = i & 63;
    int s    = (i >> 11) & 2047;
    int b    = i >> 22;
    int h    = (i >> 6) & 31;

    float c  = cosT[s*64 + pair];
    float sn = sinT[s*64 + pair];

    size_t off = ((size_t)(b*SS + s))*DD + h*HDD + pair*2;
    float2 qv = *(float2*)(q + off);
    float2 kv = *(float2*)(k + off);
    *(float2*)(q + off) = make_float2(qv.x*c - qv.y*sn, qv.x*sn + qv.y*c);
    *(float2*)(k + off) = make_float2(kv.x*c - kv.y*sn, kv.x*sn + kv.y*c);
}

// ---------------------------------------------------------------------------
// Flash attention (causal, exact fp32). One CTA = 64 query rows of one (b,h).
// 8 warps, 8 rows per warp. smem: Qs[64][128] Kt[128][64] Vs[64][128] Ps[64][64]
// = 112 KB dynamic.
// ---------------------------------------------------------------------------
__global__ __launch_bounds__(256) void flash_attn(const float* __restrict__ Q,
                                                  const float* __restrict__ K,
                                                  const float* __restrict__ V,
                                                  float* __restrict__ O)
{
    extern __shared__ float sm[];
    float* Qs = sm;                  // 64*128
    float* Kt = Qs + 64*128;         // 128*64 : Kt[d*64 + j]
    float* Vs = Kt + 128*64;         // 64*128
    float* Ps = Vs + 64*128;         // 64*64

    const int b  = blockIdx.z;
    const int h  = blockIdx.y;
    const int q0 = blockIdx.x * 64;
    const int t    = threadIdx.x;
    const int w    = t >> 5;
    const int lane = t & 31;

    {
        int r  = t >> 2;
        int c0 = (t & 3) * 32;
        const float* src = Q + ((size_t)(b*SS + q0 + r))*DD + h*HDD + c0;
        float* dst = Qs + r*128 + c0;
#pragma unroll
        for (int i = 0; i < 8; i++) ((float4*)dst)[i] = ((const float4*)src)[i];
    }

    float m[8], l[8], o[8][4];
#pragma unroll
    for (int rr = 0; rr < 8; rr++) {
        m[rr] = -INFINITY; l[rr] = 0.f;
        o[rr][0] = o[rr][1] = o[rr][2] = o[rr][3] = 0.f;
    }

    const float scale = 0.08838834764831845f;  // 1/sqrt(128)
    const int ntiles = q0/64 + 1;              // causal

    for (int kt = 0; kt < ntiles; kt++) {
        const int j0 = kt * 64;
        __syncthreads();
        {
            int r  = t >> 2;
            int c0 = (t & 3) * 32;
            size_t base = ((size_t)(b*SS + j0 + r))*DD + h*HDD + c0;
            const float* ksrc = K + base;
            const float* vsrc = V + base;
            float* vdst = Vs + r*128 + c0;
#pragma unroll
            for (int i = 0; i < 8; i++) {
                float4 kv = ((const float4*)ksrc)[i];
                int d = c0 + i*4;
                Kt[(d+0)*64 + r] = kv.x;
                Kt[(d+1)*64 + r] = kv.y;
                Kt[(d+2)*64 + r] = kv.z;
                Kt[(d+3)*64 + r] = kv.w;
                ((float4*)vdst)[i] = ((const float4*)vsrc)[i];
            }
        }
        __syncthreads();

        // ---- scores ----
        float s0[8], s1[8];
#pragma unroll
        for (int rr = 0; rr < 8; rr++) { s0[rr] = 0.f; s1[rr] = 0.f; }
#pragma unroll 4
        for (int d = 0; d < 128; d++) {
            float kv0 = Kt[d*64 + lane];
            float kv1 = Kt[d*64 + lane + 32];
#pragma unroll
            for (int rr = 0; rr < 8; rr++) {
                float qv = Qs[(w*8 + rr)*128 + d];
                s0[rr] += qv * kv0;
                s1[rr] += qv * kv1;
            }
        }

        // ---- online softmax ----
#pragma unroll
        for (int rr = 0; rr < 8; rr++) {
            int ig  = q0 + w*8 + rr;
            int jg0 = j0 + lane;
            int jg1 = j0 + lane + 32;
            float v0 = (jg0 <= ig) ? s0[rr]*scale : -INFINITY;
            float v1 = (jg1 <= ig) ? s1[rr]*scale : -INFINITY;
            float tmax = fmaxf(v0, v1);
#pragma unroll
            for (int off = 16; off; off >>= 1)
                tmax = fmaxf(tmax, __shfl_xor_sync(0xffffffffu, tmax, off));
            float newm = fmaxf(m[rr], tmax);
            float p0 = __expf(v0 - newm);
            float p1 = __expf(v1 - newm);
            float psum = p0 + p1;
#pragma unroll
            for (int off = 16; off; off >>= 1)
                psum += __shfl_xor_sync(0xffffffffu, psum, off);
            float corr = __expf(m[rr] - newm);
            l[rr] = l[rr]*corr + psum;
            m[rr] = newm;
            o[rr][0] *= corr; o[rr][1] *= corr; o[rr][2] *= corr; o[rr][3] *= corr;
            Ps[(w*8 + rr)*64 + lane]      = p0;
            Ps[(w*8 + rr)*64 + lane + 32] = p1;
        }
        __syncwarp();

        // ---- o += P @ V ----
        for (int j = 0; j < 64; j++) {
            float v0 = Vs[j*128 + lane];
            float v1 = Vs[j*128 + lane + 32];
            float v2 = Vs[j*128 + lane + 64];
            float v3 = Vs[j*128 + lane + 96];
#pragma unroll
            for (int rr = 0; rr < 8; rr++) {
                float p = Ps[(w*8 + rr)*64 + j];
                o[rr][0] += p*v0; o[rr][1] += p*v1;
                o[rr][2] += p*v2; o[rr][3] += p*v3;
            }
        }
    }

#pragma unroll
    for (int rr = 0; rr < 8; rr++) {
        float inv = 1.f / l[rr];
        size_t base = ((size_t)(b*SS + q0 + w*8 + rr))*DD + h*HDD + lane;
        O[base +  0] = o[rr][0] * inv;
        O[base + 32] = o[rr][1] * inv;
        O[base + 64] = o[rr][2] * inv;
        O[base + 96] = o[rr][3] * inv;
    }
}

// ---------------------------------------------------------------------------
// kernel_launch. inputs: 0:x 1:freqs_cos 2:freqs_sin 3:mask 4:wq 5:wk 6:wv
// 7:wo 8:cache_k 9:cache_v 10:start_pos. start_pos=0; hard causal mask is
// bit-identical to softmax(x - 1e9) in fp32 (exp underflows to 0 exactly).
// ---------------------------------------------------------------------------
extern "C" void kernel_launch(void* const* d_in, const int* in_sizes, int n_in,
                              void* d_out, int out_size)
{
    const float* x  = (const float*)d_in[0];
    const float* fc = (const float*)d_in[1];
    const float* fs = (const float*)d_in[2];
    const float* wq = (const float*)d_in[4];
    const float* wk = (const float*)d_in[5];
    const float* wv = (const float*)d_in[6];
    const float* wo = (const float*)d_in[7];
    float* out = (float*)d_out;

    float *q, *k, *v, *a;
    cudaGetSymbolAddress((void**)&q, g_q);
    cudaGetSymbolAddress((void**)&k, g_k);
    cudaGetSymbolAddress((void**)&v, g_v);
    cudaGetSymbolAddress((void**)&a, g_a);

    cudaFuncSetAttribute(flash_attn, cudaFuncAttributeMaxDynamicSharedMemorySize, 114688);

    bgemm_qkv<<<dim3(DD/128, MTOT/128, 3), 256>>>(x, wq, wk, wv);

    rope_kernel<<<(BB*SS*HH*64)/256, 256>>>(q, k, fc, fs);

    flash_attn<<<dim3(SS/64, HH, BB), 256, 114688>>>(q, k, v, a);

    bgemm_nt<<<dim3(DD/128, MTOT/128), 256>>>(a, wo, out, DD, DD);
}